// round 1
// baseline (speedup 1.0000x reference)
#include <cuda_runtime.h>
#include <stdint.h>

// TwoHotEmbedding: out[t,:] = w[i1[t],:]            if i1[t]==i2[t]
//                             w[i1[t],:] + w[i2[t],:] otherwise
// B*S = 65536 tokens, D = 256 floats (= 64 float4) per row.
// One warp per token: each lane handles 2 float4 (lane, lane+32).

static constexpr int TOKENS_EXPECTED = 16 * 4096;
static constexpr int D4 = 64;  // 256 floats / 4

__global__ __launch_bounds__(256) void twohot_kernel(
    const int* __restrict__ idx1,
    const int* __restrict__ idx2,
    const float4* __restrict__ weight,   // [NUM_EMB, 64] as float4
    float4* __restrict__ out,            // [tokens, 64] as float4
    int n_tokens)
{
    const int warp_global = (blockIdx.x * blockDim.x + threadIdx.x) >> 5;
    const int lane = threadIdx.x & 31;
    if (warp_global >= n_tokens) return;

    // Uniform per-warp loads (broadcast within warp — single sector each).
    const int a = idx1[warp_global];
    const int b = idx2[warp_global];

    const float4* __restrict__ ra = weight + (size_t)a * D4;
    const float4* __restrict__ rb = weight + (size_t)b * D4;
    float4* __restrict__ o = out + (size_t)warp_global * D4;

    const bool same = (a == b);   // warp-uniform, no divergence

    // Issue all 4 loads up-front for MLP before consuming.
    float4 va0 = ra[lane];
    float4 va1 = ra[lane + 32];
    if (same) {
        o[lane]      = va0;
        o[lane + 32] = va1;
    } else {
        float4 vb0 = rb[lane];
        float4 vb1 = rb[lane + 32];
        va0.x += vb0.x; va0.y += vb0.y; va0.z += vb0.z; va0.w += vb0.w;
        va1.x += vb1.x; va1.y += vb1.y; va1.z += vb1.z; va1.w += vb1.w;
        o[lane]      = va0;
        o[lane + 32] = va1;
    }
}

extern "C" void kernel_launch(void* const* d_in, const int* in_sizes, int n_in,
                              void* d_out, int out_size)
{
    const int* idx1 = (const int*)d_in[0];       // input_one [B,S] int32
    const int* idx2 = (const int*)d_in[1];       // input_two [B,S] int32
    const float4* weight = (const float4*)d_in[2]; // weight [100000,256] f32

    float4* out = (float4*)d_out;

    const int n_tokens = in_sizes[0];            // 65536
    (void)n_in; (void)out_size; (void)TOKENS_EXPECTED;

    // 8 warps (tokens) per block of 256 threads.
    const int warps_per_block = 256 / 32;
    const int blocks = (n_tokens + warps_per_block - 1) / warps_per_block;
    twohot_kernel<<<blocks, 256>>>(idx1, idx2, weight, out, n_tokens);
}

// round 3
// speedup vs baseline: 1.0342x; 1.0342x over previous
#include <cuda_runtime.h>
#include <stdint.h>

// TwoHotEmbedding: out[t,:] = w[i1[t],:]              if i1[t]==i2[t]
//                             w[i1[t],:] + w[i2[t],:]  otherwise
// B*S = 65536 tokens, D = 256 floats per row (1024 bytes).
// One warp per token: each lane loads 32 bytes (v8.b32, 256-bit LDG) so a
// single instruction per warp covers the whole row.
//
// Cache policy: weight gathers use L2::evict_last (keep the 102MB table
// resident in the 126MB L2 across graph replays); output stores use .cs
// (evict-first streaming) so the 67MB of write-once data doesn't evict it.

static constexpr int D4 = 64;  // 256 floats / 4 (float4 granularity)

struct V8 { float v[8]; };

__device__ __forceinline__ V8 ldg256_keep(const float* p) {
    V8 r;
    asm volatile(
        "ld.global.nc.L2::evict_last.v8.b32 {%0,%1,%2,%3,%4,%5,%6,%7}, [%8];"
        : "=f"(r.v[0]), "=f"(r.v[1]), "=f"(r.v[2]), "=f"(r.v[3]),
          "=f"(r.v[4]), "=f"(r.v[5]), "=f"(r.v[6]), "=f"(r.v[7])
        : "l"(p));
    return r;
}

__device__ __forceinline__ void stg_stream4(float* p, float a, float b, float c, float d) {
    asm volatile("st.global.cs.v4.f32 [%0], {%1,%2,%3,%4};"
                 :: "l"(p), "f"(a), "f"(b), "f"(c), "f"(d)
                 : "memory");
}

__global__ __launch_bounds__(256) void twohot_kernel(
    const int* __restrict__ idx1,
    const int* __restrict__ idx2,
    const float* __restrict__ weight,   // [NUM_EMB, 256] f32
    float* __restrict__ out,            // [tokens, 256] f32
    int n_tokens)
{
    const int warp_global = (blockIdx.x * blockDim.x + threadIdx.x) >> 5;
    const int lane = threadIdx.x & 31;
    if (warp_global >= n_tokens) return;

    // Uniform per-warp loads (broadcast within warp).
    const int a = idx1[warp_global];
    const int b = idx2[warp_global];

    const float* __restrict__ ra = weight + (size_t)a * 256 + lane * 8;
    const float* __restrict__ rb = weight + (size_t)b * 256 + lane * 8;
    float* __restrict__ o = out + (size_t)warp_global * 256 + lane * 8;

    const bool same = (a == b);   // warp-uniform, no divergence

    V8 va = ldg256_keep(ra);
    if (same) {
        stg_stream4(o,     va.v[0], va.v[1], va.v[2], va.v[3]);
        stg_stream4(o + 4, va.v[4], va.v[5], va.v[6], va.v[7]);
    } else {
        V8 vb = ldg256_keep(rb);
        #pragma unroll
        for (int i = 0; i < 8; i++) va.v[i] += vb.v[i];
        stg_stream4(o,     va.v[0], va.v[1], va.v[2], va.v[3]);
        stg_stream4(o + 4, va.v[4], va.v[5], va.v[6], va.v[7]);
    }
}

extern "C" void kernel_launch(void* const* d_in, const int* in_sizes, int n_in,
                              void* d_out, int out_size)
{
    const int* idx1 = (const int*)d_in[0];        // input_one [B,S] int32
    const int* idx2 = (const int*)d_in[1];        // input_two [B,S] int32
    const float* weight = (const float*)d_in[2];  // weight [100000,256] f32

    float* out = (float*)d_out;

    const int n_tokens = in_sizes[0];             // 65536
    (void)n_in; (void)out_size; (void)D4;

    const int warps_per_block = 256 / 32;
    const int blocks = (n_tokens + warps_per_block - 1) / warps_per_block;
    twohot_kernel<<<blocks, 256>>>(idx1, idx2, weight, out, n_tokens);
}

// round 4
// speedup vs baseline: 1.0528x; 1.0180x over previous
#include <cuda_runtime.h>
#include <stdint.h>

// TwoHotEmbedding: out[t,:] = w[i1[t],:]              if i1[t]==i2[t]
//                             w[i1[t],:] + w[i2[t],:]  otherwise
// B*S = 65536 tokens, D = 256 floats per row (1024 bytes = 32 lanes x 32B).
//
// R4: 2 tokens per warp, both rows loaded UNconditionally (i1==i2 has
// probability ~1e-5; handled by a select, not a branch). This puts 4
// independent 256-bit gathers in flight per lane before any use -> 2x MLP
// vs R3, attacking the latency/issue bound (nothing was saturated in ncu).

struct V8 { float v[8]; };

__device__ __forceinline__ V8 ldg256_keep(const float* p) {
    V8 r;
    asm volatile(
        "ld.global.nc.L2::evict_last.v8.b32 {%0,%1,%2,%3,%4,%5,%6,%7}, [%8];"
        : "=f"(r.v[0]), "=f"(r.v[1]), "=f"(r.v[2]), "=f"(r.v[3]),
          "=f"(r.v[4]), "=f"(r.v[5]), "=f"(r.v[6]), "=f"(r.v[7])
        : "l"(p));
    return r;
}

__device__ __forceinline__ void stg_stream4(float* p, float a, float b, float c, float d) {
    asm volatile("st.global.cs.v4.f32 [%0], {%1,%2,%3,%4};"
                 :: "l"(p), "f"(a), "f"(b), "f"(c), "f"(d)
                 : "memory");
}

__global__ __launch_bounds__(256) void twohot_kernel(
    const int* __restrict__ idx1,
    const int* __restrict__ idx2,
    const float* __restrict__ weight,   // [NUM_EMB, 256] f32
    float* __restrict__ out,            // [tokens, 256] f32
    int n_tokens)
{
    const int warp_global = (blockIdx.x * blockDim.x + threadIdx.x) >> 5;
    const int lane = threadIdx.x & 31;
    const int t0 = warp_global * 2;            // first of 2 tokens
    if (t0 >= n_tokens) return;

    // Paired index loads (64-bit each, warp-broadcast).
    const int2 ia = *(const int2*)(idx1 + t0);
    const int2 ib = *(const int2*)(idx2 + t0);

    const int off = lane * 8;
    const float* p1a = weight + (size_t)ia.x * 256 + off;
    const float* p2a = weight + (size_t)ib.x * 256 + off;
    const float* p1b = weight + (size_t)ia.y * 256 + off;
    const float* p2b = weight + (size_t)ib.y * 256 + off;

    // 4 independent 256-bit gathers in flight.
    V8 e1a = ldg256_keep(p1a);
    V8 e2a = ldg256_keep(p2a);
    V8 e1b = ldg256_keep(p1b);
    V8 e2b = ldg256_keep(p2b);

    const bool same_a = (ia.x == ib.x);
    const bool same_b = (ia.y == ib.y);

    float ra[8], rb[8];
    #pragma unroll
    for (int i = 0; i < 8; i++) {
        ra[i] = same_a ? e1a.v[i] : e1a.v[i] + e2a.v[i];
        rb[i] = same_b ? e1b.v[i] : e1b.v[i] + e2b.v[i];
    }

    float* oa = out + (size_t)t0 * 256 + off;
    float* ob = oa + 256;
    stg_stream4(oa,     ra[0], ra[1], ra[2], ra[3]);
    stg_stream4(oa + 4, ra[4], ra[5], ra[6], ra[7]);
    stg_stream4(ob,     rb[0], rb[1], rb[2], rb[3]);
    stg_stream4(ob + 4, rb[4], rb[5], rb[6], rb[7]);
}

extern "C" void kernel_launch(void* const* d_in, const int* in_sizes, int n_in,
                              void* d_out, int out_size)
{
    const int* idx1 = (const int*)d_in[0];        // input_one [B,S] int32
    const int* idx2 = (const int*)d_in[1];        // input_two [B,S] int32
    const float* weight = (const float*)d_in[2];  // weight [100000,256] f32

    float* out = (float*)d_out;

    const int n_tokens = in_sizes[0];             // 65536
    (void)n_in; (void)out_size;

    // 8 warps/block, 2 tokens/warp -> 16 tokens per block.
    const int tokens_per_block = 16;
    const int blocks = (n_tokens + tokens_per_block - 1) / tokens_per_block;
    twohot_kernel<<<blocks, 256>>>(idx1, idx2, weight, out, n_tokens);
}